// round 6
// baseline (speedup 1.0000x reference)
#include <cuda_runtime.h>
#include <cstdint>

// Flag: 1 if idx buffer is int64, 0 if int32.
__device__ int g_idx_is64;

// Detect idx dtype: for int64 indices in [0, 1e6) the high words are all 0;
// for random int32 indices the odd words are ~never all zero across 64 entries.
__global__ void detect_idx_kernel(const unsigned int* __restrict__ idx_words) {
    int is64 = 1;
    #pragma unroll 1
    for (int k = 0; k < 64; ++k) {
        if (idx_words[2 * k + 1] != 0u) { is64 = 0; break; }
    }
    g_idx_is64 = is64;
}

// L2 access policy: evict_last (keep values resident).
__device__ __forceinline__ unsigned long long make_evict_last_policy() {
    unsigned long long pol;
    asm volatile("createpolicy.fractional.L2::evict_last.b64 %0, 1.0;" : "=l"(pol));
    return pol;
}

__device__ __forceinline__ float ldg_L2_resident(const float* p, unsigned long long pol) {
    float v;
    asm volatile("ld.global.nc.L2::cache_hint.f32 %0, [%1], %2;"
                 : "=f"(v) : "l"(p), "l"(pol));
    return v;
}

// Two neurons per 16-lane group (doubles per-thread MLP on the gather path).
// lane d owns element d of both neurons.
__global__ __launch_bounds__(256)
void weighted_atom_kernel(const float* __restrict__ values,
                          const void*  __restrict__ idx_raw,
                          const float* __restrict__ W,
                          const float* __restrict__ bvec,
                          float* __restrict__ out,
                          int N)
{
    const int gid   = blockIdx.x * blockDim.x + threadIdx.x;
    const int group = gid >> 4;          // 16-lane group id
    const int lane  = gid & 15;
    const int n0    = group * 2;
    const int n1    = n0 + 1;
    if (n1 >= N) return;                 // grid sized exactly; never taken

    const unsigned long long pol = make_evict_last_policy();

    // ---- fetch 16 fan-in indices (2 neurons x 8) with vector loads ----
    long long rows[16];
    if (g_idx_is64) {
        const int4* p = (const int4*)((const long long*)idx_raw + (long long)n0 * 8);
        #pragma unroll
        for (int v = 0; v < 4; ++v) {            // 4 x 16B = 8 int64 per neuron pair half
            int4 q = p[v];
            rows[v * 2 + 0] = ((long long)q.y << 32) | (unsigned int)q.x;
            rows[v * 2 + 1] = ((long long)q.w << 32) | (unsigned int)q.z;
        }
        const int4* p2 = p + 4;
        #pragma unroll
        for (int v = 0; v < 4; ++v) {
            int4 q = p2[v];
            rows[8 + v * 2 + 0] = ((long long)q.y << 32) | (unsigned int)q.x;
            rows[8 + v * 2 + 1] = ((long long)q.w << 32) | (unsigned int)q.z;
        }
    } else {
        const int4* p = (const int4*)((const int*)idx_raw + n0 * 8);
        #pragma unroll
        for (int v = 0; v < 4; ++v) {            // 4 x 16B = 16 int32
            int4 q = p[v];
            rows[v * 4 + 0] = q.x;
            rows[v * 4 + 1] = q.y;
            rows[v * 4 + 2] = q.z;
            rows[v * 4 + 3] = q.w;
        }
    }

    // ---- streaming W loads for both neurons (8 x LDG.128, evict-first) ----
    const float4* W0 = (const float4*)(W + (size_t)n0 * 256 + (size_t)lane * 16);
    const float4* W1 = (const float4*)(W + (size_t)n1 * 256 + (size_t)lane * 16);
    float4 a0 = __ldcs(W0 + 0), a1 = __ldcs(W0 + 1), a2 = __ldcs(W0 + 2), a3 = __ldcs(W0 + 3);
    float4 c0 = __ldcs(W1 + 0), c1 = __ldcs(W1 + 1), c2 = __ldcs(W1 + 2), c3 = __ldcs(W1 + 3);

    float y0 = __ldcs(bvec + n0 * 16 + lane);
    float y1 = __ldcs(bvec + n1 * 16 + lane);

    // ---- gathers: 16 independent L2-resident loads, front-batched ----
    float g[16];
    #pragma unroll
    for (int k = 0; k < 16; ++k)
        g[k] = ldg_L2_resident(values + rows[k] * 16 + lane, pol);

    float s0 = 0.0f, s1 = 0.0f;
    #pragma unroll
    for (int k = 0; k < 8; ++k) { s0 += g[k]; s1 += g[8 + k]; }

    const unsigned mask = 0xFFFFFFFFu;
    // neuron 0
    y0 += a0.x * __shfl_sync(mask, s0,  0, 16);
    y0 += a0.y * __shfl_sync(mask, s0,  1, 16);
    y0 += a0.z * __shfl_sync(mask, s0,  2, 16);
    y0 += a0.w * __shfl_sync(mask, s0,  3, 16);
    y0 += a1.x * __shfl_sync(mask, s0,  4, 16);
    y0 += a1.y * __shfl_sync(mask, s0,  5, 16);
    y0 += a1.z * __shfl_sync(mask, s0,  6, 16);
    y0 += a1.w * __shfl_sync(mask, s0,  7, 16);
    y0 += a2.x * __shfl_sync(mask, s0,  8, 16);
    y0 += a2.y * __shfl_sync(mask, s0,  9, 16);
    y0 += a2.z * __shfl_sync(mask, s0, 10, 16);
    y0 += a2.w * __shfl_sync(mask, s0, 11, 16);
    y0 += a3.x * __shfl_sync(mask, s0, 12, 16);
    y0 += a3.y * __shfl_sync(mask, s0, 13, 16);
    y0 += a3.z * __shfl_sync(mask, s0, 14, 16);
    y0 += a3.w * __shfl_sync(mask, s0, 15, 16);
    // neuron 1
    y1 += c0.x * __shfl_sync(mask, s1,  0, 16);
    y1 += c0.y * __shfl_sync(mask, s1,  1, 16);
    y1 += c0.z * __shfl_sync(mask, s1,  2, 16);
    y1 += c0.w * __shfl_sync(mask, s1,  3, 16);
    y1 += c1.x * __shfl_sync(mask, s1,  4, 16);
    y1 += c1.y * __shfl_sync(mask, s1,  5, 16);
    y1 += c1.z * __shfl_sync(mask, s1,  6, 16);
    y1 += c1.w * __shfl_sync(mask, s1,  7, 16);
    y1 += c2.x * __shfl_sync(mask, s1,  8, 16);
    y1 += c2.y * __shfl_sync(mask, s1,  9, 16);
    y1 += c2.z * __shfl_sync(mask, s1, 10, 16);
    y1 += c2.w * __shfl_sync(mask, s1, 11, 16);
    y1 += c3.x * __shfl_sync(mask, s1, 12, 16);
    y1 += c3.y * __shfl_sync(mask, s1, 13, 16);
    y1 += c3.z * __shfl_sync(mask, s1, 14, 16);
    y1 += c3.w * __shfl_sync(mask, s1, 15, 16);

    __stcs(out + n0 * 16 + lane, tanhf(y0));
    __stcs(out + n1 * 16 + lane, tanhf(y1));
}

extern "C" void kernel_launch(void* const* d_in, const int* in_sizes, int n_in,
                              void* d_out, int out_size)
{
    // metadata order == setup_inputs order: values, idx, W, b
    const float* values = (const float*)d_in[0];
    const void*  idx    = d_in[1];
    const float* W      = (const float*)d_in[2];
    const float* bvec   = (const float*)d_in[3];
    float* out          = (float*)d_out;

    const int N = in_sizes[3] / 16;   // b has N*16 elements

    detect_idx_kernel<<<1, 1>>>((const unsigned int*)idx);

    const int threads = 256;
    const int groups  = N / 2;                  // one 16-lane group per 2 neurons
    const int total   = groups * 16;
    const int blocks  = (total + threads - 1) / threads;
    weighted_atom_kernel<<<blocks, threads>>>(values, idx, W, bvec, out, N);
}

// round 7
// speedup vs baseline: 1.1744x; 1.1744x over previous
#include <cuda_runtime.h>
#include <cstdint>

// Flag: 1 if idx buffer is int64, 0 if int32.
__device__ int g_idx_is64;

// Detect idx dtype: for int64 indices in [0, 1e6) the high words are all 0;
// for random int32 indices the odd words are ~never all zero across 64 entries.
__global__ void detect_idx_kernel(const unsigned int* __restrict__ idx_words) {
    int is64 = 1;
    #pragma unroll 1
    for (int k = 0; k < 64; ++k) {
        if (idx_words[2 * k + 1] != 0u) { is64 = 0; break; }
    }
    g_idx_is64 = is64;
}

// L2 access policy: evict_last (keep the 64MB values table resident in L2).
__device__ __forceinline__ unsigned long long make_evict_last_policy() {
    unsigned long long pol;
    asm volatile("createpolicy.fractional.L2::evict_last.b64 %0, 1.0;" : "=l"(pol));
    return pol;
}

__device__ __forceinline__ float ldg_L2_resident(const float* p, unsigned long long pol) {
    float v;
    asm volatile("ld.global.nc.L2::cache_hint.f32 %0, [%1], %2;"
                 : "=f"(v) : "l"(p), "l"(pol));
    return v;
}

// One neuron per 16 threads (Round-4 structure: regs=32, occ~88%).
// lane = element index d in [0,16).
//   s[d]  = sum_k values[idx[n,k]*16 + d]   (coalesced 64B gathers, L2-pinned)
//   y[d]  = b[n,d] + sum_j W[n,d,j] * s[j]  (s[j] via shfl width 16)
//   out   = tanh(y)
// idx fetched with int4 vector loads to shorten the load prologue.
__global__ __launch_bounds__(256)
void weighted_atom_kernel(const float* __restrict__ values,
                          const void*  __restrict__ idx_raw,
                          const float* __restrict__ W,
                          const float* __restrict__ bvec,
                          float* __restrict__ out,
                          int N)
{
    const int gid  = blockIdx.x * blockDim.x + threadIdx.x;
    const int n    = gid >> 4;
    const int lane = gid & 15;
    if (n >= N) return;   // grid sized exactly; never taken (keeps shfl safe)

    const unsigned long long pol = make_evict_last_policy();

    // ---- fetch the 8 fan-in row indices with vector loads ----
    long long rows[8];
    if (g_idx_is64) {
        // 8 x int64 = 64B = 4 x int4 (uniform across the 16-lane group)
        const int4* p = (const int4*)((const long long*)idx_raw + (long long)n * 8);
        int4 q0 = p[0], q1 = p[1], q2 = p[2], q3 = p[3];
        rows[0] = ((long long)q0.y << 32) | (unsigned int)q0.x;
        rows[1] = ((long long)q0.w << 32) | (unsigned int)q0.z;
        rows[2] = ((long long)q1.y << 32) | (unsigned int)q1.x;
        rows[3] = ((long long)q1.w << 32) | (unsigned int)q1.z;
        rows[4] = ((long long)q2.y << 32) | (unsigned int)q2.x;
        rows[5] = ((long long)q2.w << 32) | (unsigned int)q2.z;
        rows[6] = ((long long)q3.y << 32) | (unsigned int)q3.x;
        rows[7] = ((long long)q3.w << 32) | (unsigned int)q3.z;
    } else {
        // 8 x int32 = 32B = 2 x int4
        const int4* p = (const int4*)((const int*)idx_raw + n * 8);
        int4 q0 = p[0], q1 = p[1];
        rows[0] = q0.x; rows[1] = q0.y; rows[2] = q0.z; rows[3] = q0.w;
        rows[4] = q1.x; rows[5] = q1.y; rows[6] = q1.z; rows[7] = q1.w;
    }

    // ---- streaming loads of W (4 x LDG.128, evict-first) + b ----
    const float4* Wrow4 = (const float4*)(W + (size_t)n * 256 + (size_t)lane * 16);
    float4 w0 = __ldcs(Wrow4 + 0);
    float4 w1 = __ldcs(Wrow4 + 1);
    float4 w2 = __ldcs(Wrow4 + 2);
    float4 w3 = __ldcs(Wrow4 + 3);
    float  y  = __ldcs(bvec + gid);   // b[n*16 + lane]

    // ---- gather + fan-in sum: lane d owns element d; L2-resident ----
    float s = 0.0f;
    #pragma unroll
    for (int k = 0; k < 8; ++k) {
        s += ldg_L2_resident(values + rows[k] * 16 + lane, pol);
    }

    const unsigned mask = 0xFFFFFFFFu;
    y += w0.x * __shfl_sync(mask, s,  0, 16);
    y += w0.y * __shfl_sync(mask, s,  1, 16);
    y += w0.z * __shfl_sync(mask, s,  2, 16);
    y += w0.w * __shfl_sync(mask, s,  3, 16);
    y += w1.x * __shfl_sync(mask, s,  4, 16);
    y += w1.y * __shfl_sync(mask, s,  5, 16);
    y += w1.z * __shfl_sync(mask, s,  6, 16);
    y += w1.w * __shfl_sync(mask, s,  7, 16);
    y += w2.x * __shfl_sync(mask, s,  8, 16);
    y += w2.y * __shfl_sync(mask, s,  9, 16);
    y += w2.z * __shfl_sync(mask, s, 10, 16);
    y += w2.w * __shfl_sync(mask, s, 11, 16);
    y += w3.x * __shfl_sync(mask, s, 12, 16);
    y += w3.y * __shfl_sync(mask, s, 13, 16);
    y += w3.z * __shfl_sync(mask, s, 14, 16);
    y += w3.w * __shfl_sync(mask, s, 15, 16);

    __stcs(out + gid, tanhf(y));
}

extern "C" void kernel_launch(void* const* d_in, const int* in_sizes, int n_in,
                              void* d_out, int out_size)
{
    // metadata order == setup_inputs order: values, idx, W, b
    const float* values = (const float*)d_in[0];
    const void*  idx    = d_in[1];
    const float* W      = (const float*)d_in[2];
    const float* bvec   = (const float*)d_in[3];
    float* out          = (float*)d_out;

    const int N = in_sizes[3] / 16;   // b has N*16 elements

    detect_idx_kernel<<<1, 1>>>((const unsigned int*)idx);

    const int threads = 256;
    const int total   = N * 16;
    const int blocks  = (total + threads - 1) / threads;
    weighted_atom_kernel<<<blocks, threads>>>(values, idx, W, bvec, out, N);
}